// round 4
// baseline (speedup 1.0000x reference)
#include <cuda_runtime.h>
#include <cuda_fp16.h>
#include <math_constants.h>

// Problem constants
#define Nn 8
#define Cc 32
#define C2 (Cc / 2)       // 16 channel-pairs
#define Hh 112
#define Ww 112
#define Oo 32
#define KK 3

// Tile: 16 rows x 8 cols; one warp covers whole tile (32 lanes x 4 px) per o.
#define TI 16
#define TJ 8
#define THREADS 128
#define PR (TI + 2)          // 18 patch rows
#define PC (TJ + 2)          // 10 patch cols
#define CPW 8                // copy width in half2 (32 B rows)
#define COPY_H2 (C2 * PR * CPW)   // 2304 half2 per shifted copy
#define SX_H2 (3 * COPY_H2)       // 3 kw-shifted copies = 27648 B

#define NTW (Ww / TJ)   // 14
#define NTH (Hh / TI)   // 7
#define NTILES (Nn * NTH * NTW)   // 784

#define NTERMS 144      // C2 * 9 pair-terms per o

// meta entry: .x = offset into sx[] in half2 units (kw*COPY_H2 + (c2*PR+kh)*CPW)
//             .y = half2(w0, w1) bit pattern
__device__ uint2 g_meta[Oo * NTERMS];       // filtered (padded to mult of 4 with -inf dummies)
__device__ uint2 g_meta_full[Oo * NTERMS];  // dense list for fallback
__device__ int   g_count[Oo];

__global__ void prep_w_kernel(const float* __restrict__ w) {
    int o = threadIdx.x;
    if (o >= Oo) return;
    const __half tau_h = __float2half(0.90f);
    int cnt = 0;
    for (int c2 = 0; c2 < C2; ++c2) {
        for (int k = 0; k < 9; ++k) {
            int kh = k / 3, kw = k - 3 * kh;
            float w0 = w[(o * Cc + 2 * c2) * 9 + k];
            float w1 = w[(o * Cc + 2 * c2 + 1) * 9 + k];
            __half2 wh = __floats2half2_rn(w0, w1);
            unsigned wb = *reinterpret_cast<unsigned*>(&wh);
            unsigned off = (unsigned)(kw * COPY_H2 + (c2 * PR + kh) * CPW);
            int t = c2 * 9 + k;
            g_meta_full[o * NTERMS + t] = make_uint2(off, wb);
            if (__hge(__hmax(__low2half(wh), __high2half(wh)), tau_h)) {
                g_meta[o * NTERMS + cnt] = make_uint2(off, wb);
                ++cnt;
            }
        }
    }
    // pad to multiple of 4 with harmless dummies (w = -inf, offset 0)
    while (cnt & 3) {
        g_meta[o * NTERMS + cnt] = make_uint2(0u, 0xFC00FC00u);
        ++cnt;
    }
    g_count[o] = cnt;
}

__device__ __forceinline__ void run_terms(const uint2* __restrict__ mp, int cnt,
                                          const __half2* __restrict__ sx, int tbase,
                                          __half2 acc[4]) {
    #pragma unroll 1
    for (int t = 0; t < cnt; t += 4) {
        uint2 m0 = mp[t + 0];
        uint2 m1 = mp[t + 1];
        uint2 m2 = mp[t + 2];
        uint2 m3 = mp[t + 3];
        uint4 r0 = *reinterpret_cast<const uint4*>(sx + tbase + m0.x);
        uint4 r1 = *reinterpret_cast<const uint4*>(sx + tbase + m1.x);
        uint4 r2 = *reinterpret_cast<const uint4*>(sx + tbase + m2.x);
        uint4 r3 = *reinterpret_cast<const uint4*>(sx + tbase + m3.x);
        __half2 w0 = *reinterpret_cast<__half2*>(&m0.y);
        __half2 w1 = *reinterpret_cast<__half2*>(&m1.y);
        __half2 w2 = *reinterpret_cast<__half2*>(&m2.y);
        __half2 w3 = *reinterpret_cast<__half2*>(&m3.y);
        const unsigned* p0 = &r0.x;
        const unsigned* p1 = &r1.x;
        const unsigned* p2 = &r2.x;
        const unsigned* p3 = &r3.x;
        #pragma unroll
        for (int p = 0; p < 4; ++p) {
            __half2 x0 = *reinterpret_cast<const __half2*>(&p0[p]);
            __half2 x1 = *reinterpret_cast<const __half2*>(&p1[p]);
            __half2 x2 = *reinterpret_cast<const __half2*>(&p2[p]);
            __half2 x3 = *reinterpret_cast<const __half2*>(&p3[p]);
            __half2 a = __hmax2(__hmin2(x0, w0), __hmin2(x1, w1));
            __half2 b = __hmax2(__hmin2(x2, w2), __hmin2(x3, w3));
            acc[p] = __hmax2(acc[p], __hmax2(a, b));
        }
    }
}

__global__ void __launch_bounds__(THREADS, 8)
semiconv_kernel(const float* __restrict__ x, float* __restrict__ out) {
    __shared__ __align__(16) __half2 sx[SX_H2];   // 3 shifted copies: [s][c2][row][col]

    const int tid  = threadIdx.x;
    const int tile = blockIdx.x;

    const int tw  = tile % NTW;
    const int th  = (tile / NTW) % NTH;
    const int n   = tile / (NTW * NTH);
    const int gi0 = th * TI;
    const int gj0 = tw * TJ;

    // ---- load x patch (-inf halo), pack channel pairs, scatter into 3 shifted copies ----
    const float* xn = x + (size_t)n * Cc * Hh * Ww;
    #pragma unroll 1
    for (int idx = tid; idx < C2 * PR * PC; idx += THREADS) {
        int c2  = idx / (PR * PC);
        int rem = idx - c2 * (PR * PC);
        int rr  = rem / PC;
        int cc  = rem - rr * PC;
        int gi  = gi0 + rr - 1;
        int gj  = gj0 + cc - 1;
        float v0 = -CUDART_INF_F, v1 = -CUDART_INF_F;
        if ((unsigned)gi < (unsigned)Hh && (unsigned)gj < (unsigned)Ww) {
            const float* p = xn + ((2 * c2) * Hh + gi) * Ww + gj;
            v0 = p[0];
            v1 = p[Hh * Ww];
        }
        __half2 v = __floats2half2_rn(v0, v1);
        int rowb = (c2 * PR + rr) * CPW;
        #pragma unroll
        for (int s = 0; s < 3; ++s) {
            int q = cc - s;
            if ((unsigned)q < (unsigned)CPW)
                sx[s * COPY_H2 + rowb + q] = v;
        }
    }
    __syncthreads();

    // ---- warp = whole tile for one o at a time; lane = (row, 4-px col group) ----
    const int warp = tid >> 5;
    const int lane = tid & 31;
    const int prow = lane >> 1;
    const int pj   = (lane & 1) * 4;
    const int tbase = prow * CPW + pj;   // thread offset in half2 units (16B aligned: pj in {0,4})

    const __half2 NEGINF2 = __halves2half2(__ushort_as_half(0xFC00), __ushort_as_half(0xFC00));
    const __half tau_h = __float2half(0.90f);

    const int i = gi0 + prow;
    const int j = gj0 + pj;

    #pragma unroll 1
    for (int oo = 0; oo < 8; ++oo) {
        const int o = (warp << 3) + oo;
        __half2 acc[4] = {NEGINF2, NEGINF2, NEGINF2, NEGINF2};

        run_terms(&g_meta[o * NTERMS], g_count[o], sx, tbase, acc);

        // fallback check: if any pixel's candidate < tau, excluded terms might win
        __half c0 = __hmax(__low2half(acc[0]), __high2half(acc[0]));
        __half c1 = __hmax(__low2half(acc[1]), __high2half(acc[1]));
        __half c2h = __hmax(__low2half(acc[2]), __high2half(acc[2]));
        __half c3 = __hmax(__low2half(acc[3]), __high2half(acc[3]));
        __half cm = __hmin(__hmin(c0, c1), __hmin(c2h, c3));
        if (__any_sync(0xffffffffu, __hlt(cm, tau_h))) {
            run_terms(&g_meta_full[o * NTERMS], NTERMS, sx, tbase, acc);
            c0 = __hmax(__low2half(acc[0]), __high2half(acc[0]));
            c1 = __hmax(__low2half(acc[1]), __high2half(acc[1]));
            c2h = __hmax(__low2half(acc[2]), __high2half(acc[2]));
            c3 = __hmax(__low2half(acc[3]), __high2half(acc[3]));
        }

        float4 v;
        v.x = __half2float(c0);
        v.y = __half2float(c1);
        v.z = __half2float(c2h);
        v.w = __half2float(c3);
        *reinterpret_cast<float4*>(out + (((size_t)n * Oo + o) * Hh + i) * Ww + j) = v;
    }
}

extern "C" void kernel_launch(void* const* d_in, const int* in_sizes, int n_in,
                              void* d_out, int out_size) {
    const float* x = (const float*)d_in[0];       // (8, 32, 112, 112) fp32
    const float* w = (const float*)d_in[1];       // (32, 32, 3, 3) fp32
    float* out = (float*)d_out;                   // (8, 32, 112, 112) fp32

    prep_w_kernel<<<1, 32>>>(w);
    semiconv_kernel<<<NTILES, THREADS>>>(x, out);
}

// round 5
// speedup vs baseline: 1.3048x; 1.3048x over previous
#include <cuda_runtime.h>
#include <cuda_fp16.h>
#include <math_constants.h>

// Problem constants
#define Nn 8
#define Cc 32
#define C2 16
#define Hh 112
#define Ww 112
#define Oo 32

// Tile: 16x16 px per CTA; 8 warps; each warp = all 256 px (8 px/lane) for 4 o's.
#define TI 16
#define TJ 16
#define THREADS 256
#define PR 18          // patch rows (halo 1 each side)
#define PC 18          // patch cols filled
#define PCW 20         // padded patch row pitch in half2 (80B, keeps 16B loads aligned)
#define SX_H2 (C2 * PR * PCW)   // 5760 half2 = 23040 B

#define NTW 7
#define NTH 7
#define NTILES (Nn * NTH * NTW)   // 392

#define NPOS 144       // c2*9 + kh*3 + kw
#define NGRP 8         // 8 o-groups of 4

// Per (group, pos): 4 half2 weights for the group's 4 o's (16B).
__device__ __align__(16) uint4 g_wpk[NGRP * NPOS];
// Per (group, c2*3+kh): 12-bit mask, bit (kw*4 + oo) = term kept.
__device__ unsigned g_msk3[NGRP * C2 * 3];
// Dense per-o weights for fallback: half2 bits at [o*NPOS + pos].
__device__ unsigned g_wfull[Oo * NPOS];

__global__ void prep_w_kernel(const float* __restrict__ w) {
    int pos = threadIdx.x;          // one thread per position
    if (pos >= NPOS) return;
    int c2 = pos / 9;
    int k  = pos - c2 * 9;          // kh*3+kw
    int kh = k / 3;
    int kw = k - kh * 3;
    const __half tau = __float2half(0.90f);

    unsigned whb[Oo];
    #pragma unroll
    for (int o = 0; o < Oo; ++o) {
        float w0 = w[(o * Cc + 2 * c2) * 9 + k];
        float w1 = w[(o * Cc + 2 * c2 + 1) * 9 + k];
        __half2 h = __floats2half2_rn(w0, w1);
        unsigned b = *reinterpret_cast<unsigned*>(&h);
        g_wfull[o * NPOS + pos] = b;
        whb[o] = b;
    }
    #pragma unroll
    for (int g = 0; g < NGRP; ++g) {
        uint4 wp;
        unsigned kept = 0;
        #pragma unroll
        for (int oo = 0; oo < 4; ++oo) {
            unsigned b = whb[g * 4 + oo];
            (&wp.x)[oo] = b;
            __half2 h = *reinterpret_cast<__half2*>(&b);
            if (__hge(__hmax(__low2half(h), __high2half(h)), tau))
                kept |= 1u << oo;
        }
        g_wpk[g * NPOS + pos] = wp;
        // scatter kept bits into the (c2,kh)-packed mask word
        atomicOr(&g_msk3[g * C2 * 3 + c2 * 3 + kh], kept << (kw * 4));
    }
}

__global__ void zero_masks_kernel() {
    int i = threadIdx.x;
    if (i < NGRP * C2 * 3) g_msk3[i] = 0u;
}

// Dense recompute of one o over the full term list (rare fallback path).
__device__ __noinline__ void dense_o(const __half2* __restrict__ sx, int xb, int o,
                                     __half2 accf[8]) {
    const __half2 NI = __halves2half2(__ushort_as_half(0xFC00), __ushort_as_half(0xFC00));
    #pragma unroll
    for (int p = 0; p < 8; ++p) accf[p] = NI;
    const unsigned* wrow = &g_wfull[o * NPOS];
    #pragma unroll 1
    for (int c2 = 0; c2 < C2; ++c2) {
        #pragma unroll 1
        for (int kh = 0; kh < 3; ++kh) {
            const __half2* xr = sx + c2 * (PR * PCW) + kh * PCW + xb;
            uint4 ra = *reinterpret_cast<const uint4*>(xr);
            uint4 rb = *reinterpret_cast<const uint4*>(xr + 4);
            uint2 rc = *reinterpret_cast<const uint2*>(xr + 8);
            __half2 xv[10];
            xv[0] = *reinterpret_cast<__half2*>(&ra.x);
            xv[1] = *reinterpret_cast<__half2*>(&ra.y);
            xv[2] = *reinterpret_cast<__half2*>(&ra.z);
            xv[3] = *reinterpret_cast<__half2*>(&ra.w);
            xv[4] = *reinterpret_cast<__half2*>(&rb.x);
            xv[5] = *reinterpret_cast<__half2*>(&rb.y);
            xv[6] = *reinterpret_cast<__half2*>(&rb.z);
            xv[7] = *reinterpret_cast<__half2*>(&rb.w);
            xv[8] = *reinterpret_cast<__half2*>(&rc.x);
            xv[9] = *reinterpret_cast<__half2*>(&rc.y);
            int pbase = c2 * 9 + kh * 3;
            #pragma unroll
            for (int kw = 0; kw < 3; ++kw) {
                unsigned wb = wrow[pbase + kw];
                __half2 wv = *reinterpret_cast<__half2*>(&wb);
                #pragma unroll
                for (int p = 0; p < 8; ++p)
                    accf[p] = __hmax2(accf[p], __hmin2(xv[p + kw], wv));
            }
        }
    }
}

__global__ void __launch_bounds__(THREADS)
semiconv_kernel(const float* __restrict__ x, float* __restrict__ out) {
    __shared__ __align__(16) __half2 sx[SX_H2];

    const int tid  = threadIdx.x;
    const int tile = blockIdx.x;
    const int tw  = tile % NTW;
    const int th  = (tile / NTW) % NTH;
    const int n   = tile / (NTW * NTH);
    const int gi0 = th * TI;
    const int gj0 = tw * TJ;

    // ---- fill x patch (pack channel pairs into half2, -inf halo) ----
    const float* xn = x + (size_t)n * Cc * Hh * Ww;
    #pragma unroll 1
    for (int idx = tid; idx < C2 * PR * PC; idx += THREADS) {
        int c2  = idx / (PR * PC);
        int rem = idx - c2 * (PR * PC);
        int rr  = rem / PC;
        int cc  = rem - rr * PC;
        int gi  = gi0 + rr - 1;
        int gj  = gj0 + cc - 1;
        float v0 = -CUDART_INF_F, v1 = -CUDART_INF_F;
        if ((unsigned)gi < (unsigned)Hh && (unsigned)gj < (unsigned)Ww) {
            const float* p = xn + ((2 * c2) * Hh + gi) * Ww + gj;
            v0 = p[0];
            v1 = p[Hh * Ww];
        }
        sx[(c2 * PR + rr) * PCW + cc] = __floats2half2_rn(v0, v1);
    }
    __syncthreads();

    // ---- warp = 4 o's over the whole 16x16 tile; lane = (row, 8-px half-row) ----
    const int warp = tid >> 5;          // o-group
    const int lane = tid & 31;
    const int prow = lane >> 1;         // 0..15
    const int pj   = (lane & 1) * 8;    // 0 or 8
    const int xb   = prow * PCW + pj;   // lane's base offset in a patch plane row

    const __half2 NEGINF2 = __halves2half2(__ushort_as_half(0xFC00), __ushort_as_half(0xFC00));
    const __half  tau     = __float2half(0.90f);

    __half2 acc[4][8];
    #pragma unroll
    for (int a = 0; a < 4; ++a)
        #pragma unroll
        for (int p = 0; p < 8; ++p) acc[a][p] = NEGINF2;

    const uint4*    wpb = &g_wpk[warp * NPOS];
    const unsigned* mkb = &g_msk3[warp * C2 * 3];

    #pragma unroll 1
    for (int c2 = 0; c2 < C2; ++c2) {
        #pragma unroll 1
        for (int kh = 0; kh < 3; ++kh) {
            const __half2* xr = sx + c2 * (PR * PCW) + kh * PCW + xb;
            uint4 ra = *reinterpret_cast<const uint4*>(xr);
            uint4 rb = *reinterpret_cast<const uint4*>(xr + 4);
            uint2 rc = *reinterpret_cast<const uint2*>(xr + 8);
            __half2 xv[10];
            xv[0] = *reinterpret_cast<__half2*>(&ra.x);
            xv[1] = *reinterpret_cast<__half2*>(&ra.y);
            xv[2] = *reinterpret_cast<__half2*>(&ra.z);
            xv[3] = *reinterpret_cast<__half2*>(&ra.w);
            xv[4] = *reinterpret_cast<__half2*>(&rb.x);
            xv[5] = *reinterpret_cast<__half2*>(&rb.y);
            xv[6] = *reinterpret_cast<__half2*>(&rb.z);
            xv[7] = *reinterpret_cast<__half2*>(&rb.w);
            xv[8] = *reinterpret_cast<__half2*>(&rc.x);
            xv[9] = *reinterpret_cast<__half2*>(&rc.y);

            unsigned m3 = mkb[c2 * 3 + kh];           // warp-uniform broadcast
            int pbase = c2 * 9 + kh * 3;
            #pragma unroll
            for (int kw = 0; kw < 3; ++kw) {
                if (m3 & (0xFu << (kw * 4))) {        // any o kept at this kw?
                    uint4 wq = wpb[pbase + kw];
                    __half2 w0 = *reinterpret_cast<__half2*>(&wq.x);
                    __half2 w1 = *reinterpret_cast<__half2*>(&wq.y);
                    __half2 w2 = *reinterpret_cast<__half2*>(&wq.z);
                    __half2 w3 = *reinterpret_cast<__half2*>(&wq.w);
                    if (m3 & (1u << (kw * 4 + 0))) {
                        #pragma unroll
                        for (int p = 0; p < 8; ++p)
                            acc[0][p] = __hmax2(acc[0][p], __hmin2(xv[p + kw], w0));
                    }
                    if (m3 & (1u << (kw * 4 + 1))) {
                        #pragma unroll
                        for (int p = 0; p < 8; ++p)
                            acc[1][p] = __hmax2(acc[1][p], __hmin2(xv[p + kw], w1));
                    }
                    if (m3 & (1u << (kw * 4 + 2))) {
                        #pragma unroll
                        for (int p = 0; p < 8; ++p)
                            acc[2][p] = __hmax2(acc[2][p], __hmin2(xv[p + kw], w2));
                    }
                    if (m3 & (1u << (kw * 4 + 3))) {
                        #pragma unroll
                        for (int p = 0; p < 8; ++p)
                            acc[3][p] = __hmax2(acc[3][p], __hmin2(xv[p + kw], w3));
                    }
                }
            }
        }
    }

    // ---- epilogue: per-o reduce halves, exactness fallback, store ----
    const int i = gi0 + prow;
    const int j = gj0 + pj;
    #pragma unroll
    for (int oo = 0; oo < 4; ++oo) {
        __half px[8];
        #pragma unroll
        for (int p = 0; p < 8; ++p)
            px[p] = __hmax(__low2half(acc[oo][p]), __high2half(acc[oo][p]));
        __half cm = __hmin(__hmin(__hmin(px[0], px[1]), __hmin(px[2], px[3])),
                           __hmin(__hmin(px[4], px[5]), __hmin(px[6], px[7])));
        if (__any_sync(0xffffffffu, __hlt(cm, tau))) {
            __half2 accf[8];
            dense_o(sx, xb, warp * 4 + oo, accf);
            #pragma unroll
            for (int p = 0; p < 8; ++p)
                px[p] = __hmax(__low2half(accf[p]), __high2half(accf[p]));
        }
        float* op = out + (((size_t)n * Oo + warp * 4 + oo) * Hh + i) * Ww + j;
        float4 v0 = make_float4(__half2float(px[0]), __half2float(px[1]),
                                __half2float(px[2]), __half2float(px[3]));
        float4 v1 = make_float4(__half2float(px[4]), __half2float(px[5]),
                                __half2float(px[6]), __half2float(px[7]));
        reinterpret_cast<float4*>(op)[0] = v0;
        reinterpret_cast<float4*>(op)[1] = v1;
    }
}

extern "C" void kernel_launch(void* const* d_in, const int* in_sizes, int n_in,
                              void* d_out, int out_size) {
    const float* x = (const float*)d_in[0];       // (8, 32, 112, 112) fp32
    const float* w = (const float*)d_in[1];       // (32, 32, 3, 3) fp32
    float* out = (float*)d_out;                   // (8, 32, 112, 112) fp32

    zero_masks_kernel<<<1, 512>>>();
    prep_w_kernel<<<1, NPOS>>>(w);
    semiconv_kernel<<<NTILES, THREADS>>>(x, out);
}